// round 16
// baseline (speedup 1.0000x reference)
#include <cuda_runtime.h>
#include <cstdint>

#define N_NODES 16384
#define IN_F    256
#define OUT_F   64
#define KSPLIT  8
#define KRANGE  (N_NODES / KSPLIT)   // 2048

// h = x@W + b, pre-rounded to tf32 bit pattern: [16384][64] f32 = 4MB
__device__ float g_h[N_NODES * OUT_F];
// split-K partials: [KSPLIT][16384][64] f32 = 32MB
__device__ float g_part[KSPLIT * N_NODES * OUT_F];

__device__ __forceinline__ uint32_t f2tf32(float f) {
    uint32_t u;
    asm("cvt.rna.tf32.f32 %0, %1;" : "=r"(u) : "f"(f));
    return u;
}
__device__ __forceinline__ void cp_async16(void* sm, const void* gm) {
    uint32_t s = (uint32_t)__cvta_generic_to_shared(sm);
    asm volatile("cp.async.cg.shared.global [%0], [%1], 16;" :: "r"(s), "l"(gm));
}

#define MMA_TF32(d, a, bf)                                                    \
    asm volatile(                                                             \
        "mma.sync.aligned.m16n8k8.row.col.f32.tf32.tf32.f32 "                 \
        "{%0,%1,%2,%3}, {%4,%5,%6,%7}, {%8,%9}, {%0,%1,%2,%3};"               \
        : "+f"(d[0]), "+f"(d[1]), "+f"(d[2]), "+f"(d[3])                      \
        : "r"(a[0]), "r"(a[1]), "r"(a[2]), "r"(a[3]), "r"(bf[0]), "r"(bf[1]))

// ---------------------------------------------------------------------------
// Kernel A: g_h = rna(x @ W + b)  via tf32 mma.sync (rna on both operands)
// BM=64 (grid 256), 256 thr = 8 warps: 2M x 2N x 2K-half; BK=32, NK=8
// ---------------------------------------------------------------------------
#define L_STAGES 4
#define L_A_F4   512
#define L_H_F4   512
#define L_ST_F4  (L_A_F4 + L_H_F4)
#define L_SMEM   (L_STAGES * L_ST_F4 * 16)   // 65536

__global__ __launch_bounds__(256) void linear_kernel(
    const float* __restrict__ x, const float* __restrict__ W,
    const float* __restrict__ b)
{
    extern __shared__ float4 smem[];

    const int tid  = threadIdx.x;
    const int lane = tid & 31;
    const int wid  = tid >> 5;
    const int wm   = wid & 1;
    const int wn   = (wid >> 1) & 1;
    const int kh   = wid >> 2;
    const int g    = lane >> 2;
    const int tig  = lane & 3;

    const size_t rowBase = (size_t)blockIdx.x * 64;
    const float* gA0 = x + rowBase * IN_F;

    float acc[2][4][4];
#pragma unroll
    for (int mt = 0; mt < 2; ++mt)
#pragma unroll
        for (int nt = 0; nt < 4; ++nt)
#pragma unroll
            for (int e = 0; e < 4; ++e) acc[mt][nt][e] = 0.f;

    const int NK = IN_F / 32;       // 8

    auto issue = [&](int kt) {
        const int st = kt & (L_STAGES - 1);
        float4* As4 = smem + st * L_ST_F4;
        float4* Hs4 = As4 + L_A_F4;
        const float* gA = gA0 + kt * 32;
#pragma unroll
        for (int i = 0; i < 2; ++i) {
            int e   = i * 256 + tid;
            int row = e >> 3;
            int c4  = e & 7;
            cp_async16(&As4[row * 8 + (c4 ^ (row & 7))],
                       gA + (size_t)row * IN_F + c4 * 4);
        }
        const float* gW = W + (size_t)kt * 32 * OUT_F;
#pragma unroll
        for (int i = 0; i < 2; ++i) {
            int e  = i * 256 + tid;
            int k  = e >> 4;
            int c4 = e & 15;
            cp_async16(&Hs4[k * 16 + (c4 ^ ((k & 3) << 1))],
                       gW + k * OUT_F + c4 * 4);
        }
    };

    issue(0); asm volatile("cp.async.commit_group;");
    issue(1); asm volatile("cp.async.commit_group;");
    issue(2); asm volatile("cp.async.commit_group;");

    for (int kt = 0; kt < NK; ++kt) {
        asm volatile("cp.async.wait_group 2;");
        __syncthreads();
        if (kt + 3 < NK) issue(kt + 3);
        asm volatile("cp.async.commit_group;");

        const int st = kt & (L_STAGES - 1);
        const float* As = (const float*)(smem + st * L_ST_F4);
        const float* Hs = (const float*)(smem + st * L_ST_F4 + L_A_F4);

#pragma unroll
        for (int ks = 0; ks < 2; ++ks) {
            const int k0 = kh * 16 + ks * 8 + tig;
            const int k1 = k0 + 4;
            uint32_t afr[2][4];
#pragma unroll
            for (int mt = 0; mt < 2; ++mt) {
                int r = wm * 32 + mt * 16 + g;
                afr[mt][0] = f2tf32(As[r * 32       + (((k0 >> 2) ^ (r & 7)) << 2) + (k0 & 3)]);
                afr[mt][1] = f2tf32(As[(r + 8) * 32 + (((k0 >> 2) ^ (r & 7)) << 2) + (k0 & 3)]);
                afr[mt][2] = f2tf32(As[r * 32       + (((k1 >> 2) ^ (r & 7)) << 2) + (k1 & 3)]);
                afr[mt][3] = f2tf32(As[(r + 8) * 32 + (((k1 >> 2) ^ (r & 7)) << 2) + (k1 & 3)]);
            }
            uint32_t bfr[4][2];
#pragma unroll
            for (int nt = 0; nt < 4; ++nt) {
                int n = wn * 32 + nt * 8 + g;
                bfr[nt][0] = f2tf32(Hs[k0 * 64 + (n ^ ((k0 & 3) << 3))]);
                bfr[nt][1] = f2tf32(Hs[k1 * 64 + (n ^ ((k1 & 3) << 3))]);
            }
#pragma unroll
            for (int mt = 0; mt < 2; ++mt)
#pragma unroll
                for (int nt = 0; nt < 4; ++nt)
                    MMA_TF32(acc[mt][nt], afr[mt], bfr[nt]);
        }
    }

    __syncthreads();
    float4* red = smem;
    const int wq = wid & 3;
    if (kh == 1) {
#pragma unroll
        for (int mt = 0; mt < 2; ++mt)
#pragma unroll
            for (int nt = 0; nt < 4; ++nt)
                red[((wq * 2 + mt) * 4 + nt) * 32 + lane] =
                    make_float4(acc[mt][nt][0], acc[mt][nt][1],
                                acc[mt][nt][2], acc[mt][nt][3]);
    }
    __syncthreads();
    if (kh == 0) {
#pragma unroll
        for (int mt = 0; mt < 2; ++mt) {
            size_t r = rowBase + wm * 32 + mt * 16 + g;
#pragma unroll
            for (int nt = 0; nt < 4; ++nt) {
                float4 o = red[((wq * 2 + mt) * 4 + nt) * 32 + lane];
                int c = wn * 32 + nt * 8 + tig * 2;
                float b0 = b[c], b1 = b[c + 1];
                float2 v0, v1;
                v0.x = __uint_as_float(f2tf32(acc[mt][nt][0] + o.x + b0));
                v0.y = __uint_as_float(f2tf32(acc[mt][nt][1] + o.y + b1));
                v1.x = __uint_as_float(f2tf32(acc[mt][nt][2] + o.z + b0));
                v1.y = __uint_as_float(f2tf32(acc[mt][nt][3] + o.w + b1));
                *(float2*)&g_h[r * OUT_F + c]       = v0;
                *(float2*)&g_h[(r + 8) * OUT_F + c] = v1;
            }
        }
    }
}

// ---------------------------------------------------------------------------
// Kernel B: g_part[kz] = adj[:, kz-slice] @ h[kz-slice]   (tf32 mma.sync)
// BM=256, BN=64, BK=32; grid (64, 8); 512 thr = 16 warps: 8M x 2N (32x32 tile)
// 5-stage cp.async pipeline (200KB smem, 1 CTA/SM, fill-ahead 4)
// A: raw f32 bits (HW tf32 trunc); H pre-rounded rna
// ---------------------------------------------------------------------------
#define STAGES 5
#define BK     32
#define A_ST_F4 2048                // 256 x 32 f32 = 32KB
#define H_ST_F4 512                 // 32 x 64 f32 = 8KB
#define ST_F4   (A_ST_F4 + H_ST_F4)
#define SMEM_BYTES (STAGES * ST_F4 * 16)   // 204800

__global__ __launch_bounds__(512, 1) void agg_kernel(
    const float* __restrict__ adj)
{
    extern __shared__ float4 smem[];

    const int tid   = threadIdx.x;
    const int lane  = tid & 31;
    const int wid   = tid >> 5;
    const int warpM = wid & 7;          // 8 M octants (32 rows each)
    const int warpN = wid >> 3;         // 2 N halves (32 cols each)
    const int g     = lane >> 2;
    const int tig   = lane & 3;

    const int    kz      = blockIdx.y;
    const size_t rowBase = (size_t)blockIdx.x * 256;
    const float* gA0 = adj + rowBase * N_NODES + (size_t)kz * KRANGE;
    const float* gH0 = g_h + (size_t)kz * KRANGE * OUT_F;

    float acc[2][4][4];
#pragma unroll
    for (int mt = 0; mt < 2; ++mt)
#pragma unroll
        for (int nt = 0; nt < 4; ++nt)
#pragma unroll
            for (int e = 0; e < 4; ++e) acc[mt][nt][e] = 0.f;

    const int NK = KRANGE / BK;         // 64

    auto issue = [&](int kt, int st) {
        float4* As4 = smem + st * ST_F4;             // [256][8]  swizzled
        float4* Hs4 = As4 + A_ST_F4;                 // [32][16]  swizzled
        const float* gA = gA0 + kt * BK;
#pragma unroll
        for (int i = 0; i < 4; ++i) {                // 256x32 = 2048 float4
            int e   = i * 512 + tid;
            int row = e >> 3;
            int c4  = e & 7;
            cp_async16(&As4[row * 8 + (c4 ^ (row & 7))],
                       gA + (size_t)row * N_NODES + c4 * 4);
        }
        const float* gH = gH0 + (size_t)kt * BK * OUT_F;
        {                                            // 32x64 = 512 float4
            int k  = tid >> 4;
            int c4 = tid & 15;
            cp_async16(&Hs4[k * 16 + (c4 ^ ((k & 3) << 1))],
                       gH + k * OUT_F + c4 * 4);
        }
    };

    issue(0, 0); asm volatile("cp.async.commit_group;");
    issue(1, 1); asm volatile("cp.async.commit_group;");
    issue(2, 2); asm volatile("cp.async.commit_group;");
    issue(3, 3); asm volatile("cp.async.commit_group;");

    int cs = 0;                         // consume stage = kt % 5
    for (int kt = 0; kt < NK; ++kt) {
        asm volatile("cp.async.wait_group 3;");
        __syncthreads();
        if (kt + 4 < NK) {
            int fs = cs ? cs - 1 : STAGES - 1;   // (kt+4) % 5
            issue(kt + 4, fs);
        }
        asm volatile("cp.async.commit_group;");  // uniform group count

        const uint32_t* As = (const uint32_t*)(smem + cs * ST_F4);
        const uint32_t* Hs = (const uint32_t*)(smem + cs * ST_F4 + A_ST_F4);

#pragma unroll
        for (int ks = 0; ks < 4; ++ks) {
            const int k0 = ks * 8 + tig;
            const int k1 = k0 + 4;
            // A element (r,k) at word r*32 + (((k>>2)^(r&7))<<2) + (k&3)
            uint32_t afr[2][4];
#pragma unroll
            for (int mt = 0; mt < 2; ++mt) {
                int r = warpM * 32 + mt * 16 + g;
                afr[mt][0] = As[r * 32       + (((k0 >> 2) ^ (r & 7)) << 2) + (k0 & 3)];
                afr[mt][1] = As[(r + 8) * 32 + (((k0 >> 2) ^ (r & 7)) << 2) + (k0 & 3)];
                afr[mt][2] = As[r * 32       + (((k1 >> 2) ^ (r & 7)) << 2) + (k1 & 3)];
                afr[mt][3] = As[(r + 8) * 32 + (((k1 >> 2) ^ (r & 7)) << 2) + (k1 & 3)];
            }
            // H element (k,n) at word k*64 + (n ^ ((k&3)<<3)); pre-rounded rna
            uint32_t bfr[4][2];
#pragma unroll
            for (int nt = 0; nt < 4; ++nt) {
                int n = warpN * 32 + nt * 8 + g;
                bfr[nt][0] = Hs[k0 * 64 + (n ^ ((k0 & 3) << 3))];
                bfr[nt][1] = Hs[k1 * 64 + (n ^ ((k1 & 3) << 3))];
            }
#pragma unroll
            for (int mt = 0; mt < 2; ++mt)
#pragma unroll
                for (int nt = 0; nt < 4; ++nt)
                    MMA_TF32(acc[mt][nt], afr[mt], bfr[nt]);
        }

        cs = (cs + 1 == STAGES) ? 0 : cs + 1;
    }

    // direct partial store
    float* part = g_part + (size_t)kz * N_NODES * OUT_F;
#pragma unroll
    for (int mt = 0; mt < 2; ++mt) {
        size_t r = rowBase + warpM * 32 + mt * 16 + g;
#pragma unroll
        for (int nt = 0; nt < 4; ++nt) {
            int c = warpN * 32 + nt * 8 + tig * 2;
            float2 v0, v1;
            v0.x = acc[mt][nt][0];
            v0.y = acc[mt][nt][1];
            v1.x = acc[mt][nt][2];
            v1.y = acc[mt][nt][3];
            *(float2*)&part[r * OUT_F + c]       = v0;
            *(float2*)&part[(r + 8) * OUT_F + c] = v1;
        }
    }
}

// ---------------------------------------------------------------------------
// Kernel C: out = relu(sum_kz g_part[kz])
// ---------------------------------------------------------------------------
__global__ __launch_bounds__(256) void reduce_kernel(float* __restrict__ out)
{
    const int S = N_NODES * OUT_F / 4;     // 262144 float4
    int i = blockIdx.x * 256 + threadIdx.x;
    const float4* p = (const float4*)g_part;
    float4 v = p[i];
#pragma unroll
    for (int z = 1; z < KSPLIT; ++z) {
        float4 t = p[i + z * S];
        v.x += t.x; v.y += t.y; v.z += t.z; v.w += t.w;
    }
    v.x = fmaxf(v.x, 0.f);
    v.y = fmaxf(v.y, 0.f);
    v.z = fmaxf(v.z, 0.f);
    v.w = fmaxf(v.w, 0.f);
    ((float4*)out)[i] = v;
}

// ---------------------------------------------------------------------------
extern "C" void kernel_launch(void* const* d_in, const int* in_sizes, int n_in,
                              void* d_out, int out_size)
{
    const float* x   = (const float*)d_in[0];   // [16384, 256]
    const float* adj = (const float*)d_in[1];   // [16384, 16384]
    const float* W   = (const float*)d_in[2];   // [256, 64]
    const float* b   = (const float*)d_in[3];   // [64]
    float* out = (float*)d_out;                 // [16384, 64]

    cudaFuncSetAttribute(linear_kernel,
                         cudaFuncAttributeMaxDynamicSharedMemorySize, L_SMEM);
    cudaFuncSetAttribute(agg_kernel,
                         cudaFuncAttributeMaxDynamicSharedMemorySize, SMEM_BYTES);

    linear_kernel<<<N_NODES / 64, 256, L_SMEM>>>(x, W, b);
    dim3 grid(N_NODES / 256, KSPLIT);
    agg_kernel<<<grid, 512, SMEM_BYTES>>>(adj);
    reduce_kernel<<<N_NODES * OUT_F / 4 / 256, 256>>>(out);
}